// round 1
// baseline (speedup 1.0000x reference)
#include <cuda_runtime.h>
#include <cstdint>

#define N_UNARY 128
#define NB      64
#define DROW    (2 * N_UNARY + NB)   // 320 floats per deltas row

// ---------------------------------------------------------------------------
// Kernel 1: zero the `out` accumulator region (N * 128 floats).
// d_out is poisoned to 0xAA by the harness; reference starts from zeros.
// ---------------------------------------------------------------------------
__global__ void zero_out_kernel(float4* __restrict__ out4, long long n4) {
    long long i = (long long)blockIdx.x * blockDim.x + threadIdx.x;
    long long stride = (long long)gridDim.x * blockDim.x;
    for (; i < n4; i += stride) {
        out4[i] = make_float4(0.f, 0.f, 0.f, 0.f);
    }
}

// ---------------------------------------------------------------------------
// Kernel 2: one warp per edge.
//   lane l: ux float4  = deltas[e][ l*4 .. l*4+3 ]        -> red.v4 to out[i1]
//           uy float4  = deltas[e][128 + l*4 ..]          -> red.v4 to out[i2]
//   lanes 0..15: b float4 = deltas[e][256 + l*4 ..]       -> streaming store
// deltas is read exactly once -> __ldcs keeps it from evicting the L2-resident
// `out` accumulator (51.2 MB, fits in 126 MB L2). b writes are also streaming.
// ---------------------------------------------------------------------------
__device__ __forceinline__ void red_add_v4(float* addr, float4 v) {
    asm volatile("red.global.add.v4.f32 [%0], {%1, %2, %3, %4};"
                 :: "l"(addr), "f"(v.x), "f"(v.y), "f"(v.z), "f"(v.w)
                 : "memory");
}

__global__ void __launch_bounds__(256, 8)
scatter_kernel(const float* __restrict__ deltas,
               const int*   __restrict__ index1,
               const int*   __restrict__ index2,
               float* __restrict__ out,        // [N, 128]
               float* __restrict__ outB,       // [E, 64]
               int E) {
    int warp_id = (blockIdx.x * blockDim.x + threadIdx.x) >> 5;
    if (warp_id >= E) return;
    int lane = threadIdx.x & 31;

    const float4* row = reinterpret_cast<const float4*>(deltas + (size_t)warp_id * DROW);

    int i1 = __ldg(index1 + warp_id);
    int i2 = __ldg(index2 + warp_id);

    // ux: floats [0,128) = float4 slots [0,32)
    float4 a = __ldcs(row + lane);
    // uy: floats [128,256) = float4 slots [32,64)
    float4 c = __ldcs(row + 32 + lane);

    float* dst1 = out + (size_t)i1 * N_UNARY + lane * 4;
    float* dst2 = out + (size_t)i2 * N_UNARY + lane * 4;
    red_add_v4(dst1, a);
    red_add_v4(dst2, c);

    // b: floats [256,320) = float4 slots [64,80) -> 16 float4, lanes 0..15
    if (lane < 16) {
        float4 bb = __ldcs(row + 64 + lane);
        __stcs(reinterpret_cast<float4*>(outB + (size_t)warp_id * NB) + lane, bb);
    }
}

// ---------------------------------------------------------------------------
// Launch contract
// Inputs (metadata order): unary [N,128] f32, binary [E,64] f32,
//                          deltas [E,320] f32, index1 [E,1] i32, index2 [E,1] i32
// Output buffer: [ out (N*128 f32) | b (E*64 f32) ]
// ---------------------------------------------------------------------------
extern "C" void kernel_launch(void* const* d_in, const int* in_sizes, int n_in,
                              void* d_out, int out_size) {
    const float* deltas = (const float*)d_in[2];
    const int*   index1 = (const int*)d_in[3];
    const int*   index2 = (const int*)d_in[4];

    int N = in_sizes[0] / N_UNARY;      // 100000
    int E = in_sizes[3];                // 500000 (index1 element count)

    float* out  = (float*)d_out;
    float* outB = out + (size_t)N * N_UNARY;

    // 1) zero the accumulator region
    long long n4 = (long long)N * N_UNARY / 4;
    int zb = (int)((n4 + 255) / 256);
    if (zb > 65535) zb = 65535;
    zero_out_kernel<<<zb, 256>>>(reinterpret_cast<float4*>(out), n4);

    // 2) scatter-add + b copy (one warp per edge, 8 warps per block)
    int blocks = (E + 7) / 8;
    scatter_kernel<<<blocks, 256>>>(deltas, index1, index2, out, outB, E);
}